// round 3
// baseline (speedup 1.0000x reference)
#include <cuda_runtime.h>

// EKVConv2d: out[b,o,h,w] = ALPHA * sum_{c,kh,kw} [ sp(clip(d*inv))^2 - sp(clip((d-VD)*inv))^2 ]
//   d = x_patch - theta[o, c*9+kh*3+kw],  inv = 1/(1.5*0.026),  VD = 0.1, clip to [-30,30]
// Exact-zero structure: if d*inv <= -30, BOTH args clip to -30 -> term == 0 exactly.
// Only ~1.2% of pairs are in the active band, so we branch on (a1 > -30).

#define W_ 64
#define H_ 64
#define C_ 16
#define O_ 32
#define B_ 4
#define OG 4      // output channels per block
#define HT 2      // output rows per block

__device__ __forceinline__ float sp_from_e(float e) {
    // softplus given e = exp(clipped_arg); accurate for all e in [exp(-30), exp(30)]
    if (e < 0.04f) {
        // log1p(e) = e*(1 - e/2 + e^2/3 - e^3/4), rel err < 1e-6 for e < 0.04
        return e * (1.0f + e * (-0.5f + e * (0.33333334f - 0.25f * e)));
    }
    return __logf(1.0f + e);
}

__global__ __launch_bounds__(128) void ekv_kernel(const float* __restrict__ x,
                                                  const float* __restrict__ theta,
                                                  float* __restrict__ out) {
    const float INV   = 25.641025641f;   // 1/(1.5*0.026)
    const float VDI   = 2.5641025641f;   // 0.1 * INV
    const float ALPHA = 0.0005625f;

    __shared__ float xs[C_][HT + 2][W_ + 2];   // pre-scaled by INV, zero-padded halo
    __shared__ float ths[OG][C_ * 9];          // pre-scaled by INV

    const int tid = threadIdx.x;
    const int og  = blockIdx.x;          // 0..O_/OG-1
    const int h0  = blockIdx.y * HT;     // first output row of tile
    const int b   = blockIdx.z;
    const int o0  = og * OG;

    // ---- load x tile (with halo, scaled by INV, zero padding) ----
    const float* xb = x + b * (C_ * H_ * W_);
    const int TILE = C_ * (HT + 2) * (W_ + 2);
    for (int i = tid; i < TILE; i += 128) {
        int c   = i / ((HT + 2) * (W_ + 2));
        int rem = i - c * ((HT + 2) * (W_ + 2));
        int r   = rem / (W_ + 2);
        int col = rem - r * (W_ + 2);
        int gh = h0 - 1 + r;
        int gw = col - 1;
        float v = 0.0f;
        if (gh >= 0 && gh < H_ && gw >= 0 && gw < W_)
            v = xb[(c * H_ + gh) * W_ + gw] * INV;
        (&xs[0][0][0])[i] = v;
    }
    // ---- load theta slice (scaled by INV) ----
    for (int i = tid; i < OG * C_ * 9; i += 128) {
        int o = i / (C_ * 9);
        int j = i - o * (C_ * 9);
        ths[o][j] = theta[(o0 + o) * (C_ * 9) + j] * INV;
    }
    __syncthreads();

    const int tx = tid & (W_ - 1);   // 0..63
    const int ty = tid >> 6;         // 0..HT-1

    float acc[OG];
#pragma unroll
    for (int o = 0; o < OG; o++) acc[o] = 0.0f;

#pragma unroll 1
    for (int c = 0; c < C_; c++) {
        float xv[9];
#pragma unroll
        for (int dh = 0; dh < 3; dh++)
#pragma unroll
            for (int dw = 0; dw < 3; dw++)
                xv[dh * 3 + dw] = xs[c][ty + dh][tx + dw];

#pragma unroll
        for (int o = 0; o < OG; o++) {
            float th[9];
#pragma unroll
            for (int k = 0; k < 9; k++) th[k] = ths[o][c * 9 + k];
#pragma unroll
            for (int k = 0; k < 9; k++) {
                float a1 = xv[k] - th[k];
                if (a1 > -30.0f) {      // else term is EXACTLY zero (both args clip to -30)
                    float a1c = fminf(a1, 30.0f);
                    float a2c = fminf(fmaxf(a1 - VDI, -30.0f), 30.0f);
                    float e1 = __expf(a1c);
                    float e2 = __expf(a2c);
                    float s1 = sp_from_e(e1);
                    float s2 = sp_from_e(e2);
                    acc[o] += s1 * s1 - s2 * s2;
                }
            }
        }
    }

    const int h = h0 + ty;
#pragma unroll
    for (int o = 0; o < OG; o++)
        out[(((b * O_) + o0 + o) * H_ + h) * W_ + tx] = ALPHA * acc[o];
}

extern "C" void kernel_launch(void* const* d_in, const int* in_sizes, int n_in,
                              void* d_out, int out_size) {
    const float* x     = (const float*)d_in[0];
    const float* theta = (const float*)d_in[1];
    float* out         = (float*)d_out;
    dim3 grid(O_ / OG, H_ / HT, B_);
    ekv_kernel<<<grid, 128>>>(x, theta, out);
}

// round 8
// speedup vs baseline: 2.7150x; 2.7150x over previous
#include <cuda_runtime.h>

// EKVConv2d, warp-per-pixel / lane-per-output-channel formulation.
//
// out[b,o,h,w] = ALPHA * sum_{c,kh,kw} [ sp(clip(d*inv))^2 - sp(clip((d-VD)*inv))^2 ]
//   d = x_patch - theta[o, c*9+kh*3+kw],  inv = 1/(1.5*0.026), VD=0.1, clip [-30,30]
//
// Exact-zero structure: if d*inv <= -30 then BOTH args clip to -30, s1==s2, term == 0
// exactly. A (c,k) patch element can contribute to ANY o only if
//   x*inv > min_o(theta[o,ck])*inv - 30     (data-derived threshold, no assumptions)
// Only ~5% of patch elements pass for any o. The warp scans the 144 patch values
// (warp-uniform per pixel), compacts active ones via ballot, and evaluates them
// branchlessly across all 32 lanes (lane = o), preserving exact zeros.

#define W_ 64
#define H_ 64
#define C_ 16
#define O_ 32
#define B_ 4
#define WSEG 32          // pixels (w) per block
#define TW (WSEG + 2)    // tile width with halo = 34
#define FULLMASK 0xffffffffu

__device__ __forceinline__ float sp_branchless(float e) {
    // softplus given e = exp(clipped_arg), e in [exp(-30), exp(30)]
    // poly: log1p(e) = e - e^2/2 + e^3/3 - e^4/4  (rel err < 1e-6 for e < 0.04)
    float p = e * fmaf(e, fmaf(e, fmaf(e, -0.25f, 0.33333334f), -0.5f), 1.0f);
    float l = __logf(1.0f + e);
    return (e < 0.04f) ? p : l;
}

__global__ __launch_bounds__(128) void ekv_kernel(const float* __restrict__ x,
                                                  const float* __restrict__ theta,
                                                  float* __restrict__ out) {
    const float INV   = 25.641026f;    // 1/(1.5*0.026)
    const float VDI   = 2.5641026f;    // 0.1 * INV
    const float ALPHA = 0.0005625f;

    __shared__ float thT[144 * 33];        // theta*INV transposed: [ck][o], stride 33 (conflict-free)
    __shared__ float thr[160];             // per-ck activation threshold (padded)
    __shared__ int   dtab[160];            // ck -> offset into x tile (padded)
    __shared__ float xt[C_ * 3 * TW];      // x*INV tile: [c][row(3)][col(34)]

    const int tid  = threadIdx.x;
    const int lane = tid & 31;
    const int wid  = tid >> 5;
    const int w0 = blockIdx.x * WSEG;
    const int h  = blockIdx.y;
    const int b  = blockIdx.z;

    // ---- theta -> smem transposed+scaled, per-ck min threshold on the fly ----
    for (int ck = tid; ck < 144; ck += 128) {
        float m = 1e30f;
#pragma unroll
        for (int o = 0; o < O_; ++o) {
            float t = theta[o * 144 + ck] * INV;
            thT[ck * 33 + o] = t;
            m = fminf(m, t);
        }
        thr[ck] = m - 30.0f;

        int c  = ck / 9;
        int k  = ck - 9 * c;
        int dh = k / 3;
        int dw = k - 3 * dh;
        dtab[ck] = c * (3 * TW) + dh * TW + dw;
    }
    if (tid < 16) { dtab[144 + tid] = 0; thr[144 + tid] = 1e30f; }

    // ---- x tile (rows h-1..h+1, cols w0-1..w0+32), scaled, zero-padded ----
    for (int i = tid; i < C_ * 3 * TW; i += 128) {
        int c   = i / (3 * TW);
        int rem = i - c * (3 * TW);
        int r   = rem / TW;
        int col = rem - r * TW;
        int gh = h - 1 + r;
        int gw = w0 - 1 + col;
        float v = 0.0f;
        if ((unsigned)gh < (unsigned)H_ && (unsigned)gw < (unsigned)W_)
            v = x[((b * C_ + c) * H_ + gh) * W_ + gw] * INV;
        xt[i] = v;
    }
    __syncthreads();

    // ---- main: warp wid handles pixels pl = wid*8 .. wid*8+7, lane = o ----
#pragma unroll 1
    for (int j = 0; j < 8; ++j) {
        const int pl = wid * 8 + j;          // local pixel (tile col = pl..pl+2)
        float acc = 0.0f;

#pragma unroll
        for (int it = 0; it < 5; ++it) {
            const int ckbase = it * 32;
            const int ck = ckbase + lane;    // up to 159; padded entries never pass
            float xv = xt[pl + dtab[ck]];
            unsigned m = __ballot_sync(FULLMASK, xv > thr[ck]);
            while (m) {
                int src = __ffs(m) - 1;
                m &= m - 1;
                float xb  = __shfl_sync(FULLMASK, xv, src);
                float th  = thT[(ckbase + src) * 33 + lane];
                float a1  = xb - th;
                float a1c = fminf(fmaxf(a1, -30.0f), 30.0f);
                float a2c = fminf(fmaxf(a1 - VDI, -30.0f), 30.0f);
                float e1 = __expf(a1c);
                float e2 = __expf(a2c);
                float s1 = sp_branchless(e1);
                float s2 = sp_branchless(e2);
                // forced FMUL/FSUB (no FFMA contraction) so s1==s2 -> exactly 0
                float t = __fsub_rn(__fmul_rn(s1, s1), __fmul_rn(s2, s2));
                acc = __fadd_rn(acc, t);
            }
        }

        const int w = w0 + pl;
        out[((b * O_ + lane) * H_ + h) * W_ + w] = ALPHA * acc;
    }
}

extern "C" void kernel_launch(void* const* d_in, const int* in_sizes, int n_in,
                              void* d_out, int out_size) {
    const float* x     = (const float*)d_in[0];
    const float* theta = (const float*)d_in[1];
    float* out         = (float*)d_out;
    dim3 grid(W_ / WSEG, H_, B_);   // (2, 64, 4) = 512 CTAs
    ekv_kernel<<<grid, 128>>>(x, theta, out);
}

// round 9
// speedup vs baseline: 2.9443x; 1.0845x over previous
#include <cuda_runtime.h>

// EKVConv2d, warp-per-pixel / lane-per-output-channel, ballot-compacted.
//
// out[b,o,h,w] = ALPHA * sum_{c,kh,kw} [ sp(clip(d*inv))^2 - sp(clip((d-VD)*inv))^2 ]
//   d = x_patch - theta[o, c*9+kh*3+kw],  inv = 1/(1.5*0.026), VD=0.1, clip [-30,30]
//
// Exact-zero structure: if d*inv <= -30 then BOTH args clip to -30, s1==s2, term==0
// exactly. Patch element (c,k) can contribute to ANY o only if
//   x*inv > min_o(theta[o,ck]*inv) - 30    (data-derived threshold)
// ~5% of elements pass; warp scans 144 elems per pixel once (warp-uniform),
// ballot-compacts, evaluates actives branchlessly across lanes (lane = o).
//
// R9: 256-thread blocks (8 warps x 4 pixels) for 2x occupancy; dtab/thr hoisted
// to registers (invariant across pixels).

#define W_ 64
#define H_ 64
#define C_ 16
#define O_ 32
#define B_ 4
#define WSEG 32          // pixels (w) per block
#define TW (WSEG + 2)    // tile width with halo = 34
#define NT 256           // threads per block
#define PXW 4            // pixels per warp
#define FULLMASK 0xffffffffu

__device__ __forceinline__ float sp_branchless(float e) {
    // softplus given e = exp(clipped_arg), e in [exp(-30), exp(30)]
    // poly: log1p(e) ~= e*(1 - e/2 + e^2/3 - e^3/4), rel err < 1e-6 for e < 0.04
    float p = e * fmaf(e, fmaf(e, fmaf(e, -0.25f, 0.33333334f), -0.5f), 1.0f);
    float l = __logf(1.0f + e);
    return (e < 0.04f) ? p : l;
}

__global__ __launch_bounds__(NT) void ekv_kernel(const float* __restrict__ x,
                                                 const float* __restrict__ theta,
                                                 float* __restrict__ out) {
    const float INV   = 25.641026f;    // 1/(1.5*0.026)
    const float VDI   = 2.5641026f;    // 0.1 * INV
    const float ALPHA = 0.0005625f;

    __shared__ float thT[144 * 33];        // theta*INV transposed: [ck][o], stride 33
    __shared__ float thr[160];             // per-ck activation threshold (padded)
    __shared__ int   dtab[160];            // ck -> offset into x tile (padded)
    __shared__ float xt[C_ * 3 * TW];      // x*INV tile: [c][row(3)][col(34)]

    const int tid  = threadIdx.x;
    const int lane = tid & 31;
    const int wid  = tid >> 5;             // 0..7
    const int w0 = blockIdx.x * WSEG;
    const int h  = blockIdx.y;
    const int b  = blockIdx.z;

    // ---- theta -> smem transposed+scaled, per-ck min threshold on the fly ----
    for (int ck = tid; ck < 144; ck += NT) {
        float m = 1e30f;
#pragma unroll
        for (int o = 0; o < O_; ++o) {
            float t = theta[o * 144 + ck] * INV;
            thT[ck * 33 + o] = t;
            m = fminf(m, t);
        }
        thr[ck] = m - 30.0f;

        int c  = ck / 9;
        int k  = ck - 9 * c;
        int dh = k / 3;
        int dw = k - 3 * dh;
        dtab[ck] = c * (3 * TW) + dh * TW + dw;
    }
    if (tid < 16) { dtab[144 + tid] = 0; thr[144 + tid] = 1e30f; }

    // ---- x tile (rows h-1..h+1, cols w0-1..w0+32), scaled, zero-padded ----
    for (int i = tid; i < C_ * 3 * TW; i += NT) {
        int c   = i / (3 * TW);
        int rem = i - c * (3 * TW);
        int r   = rem / TW;
        int col = rem - r * TW;
        int gh = h - 1 + r;
        int gw = w0 - 1 + col;
        float v = 0.0f;
        if ((unsigned)gh < (unsigned)H_ && (unsigned)gw < (unsigned)W_)
            v = x[((b * C_ + c) * H_ + gh) * W_ + gw] * INV;
        xt[i] = v;
    }
    __syncthreads();

    // ---- hoist per-lane scan constants (invariant across pixels) ----
    int   rdtab[5];
    float rthr[5];
#pragma unroll
    for (int it = 0; it < 5; ++it) {
        rdtab[it] = dtab[it * 32 + lane];
        rthr[it]  = thr[it * 32 + lane];
    }

    // ---- main: warp wid handles pixels pl = wid*PXW .. +PXW-1, lane = o ----
#pragma unroll 1
    for (int j = 0; j < PXW; ++j) {
        const int pl = wid * PXW + j;        // local pixel (tile cols pl..pl+2)
        float acc = 0.0f;

#pragma unroll
        for (int it = 0; it < 5; ++it) {
            const int ckbase = it * 32;
            float xv = xt[pl + rdtab[it]];
            unsigned m = __ballot_sync(FULLMASK, xv > rthr[it]);
            while (m) {
                int src = __ffs(m) - 1;
                m &= m - 1;
                float xb  = __shfl_sync(FULLMASK, xv, src);
                float th  = thT[(ckbase + src) * 33 + lane];
                float a1  = xb - th;
                float a1c = fminf(fmaxf(a1, -30.0f), 30.0f);
                float a2c = fminf(fmaxf(a1 - VDI, -30.0f), 30.0f);
                float e1 = __expf(a1c);
                float e2 = __expf(a2c);
                float s1 = sp_branchless(e1);
                float s2 = sp_branchless(e2);
                // forced FMUL/FSUB (no FFMA contraction) so s1==s2 -> exactly 0
                float t = __fsub_rn(__fmul_rn(s1, s1), __fmul_rn(s2, s2));
                acc = __fadd_rn(acc, t);
            }
        }

        const int w = w0 + pl;
        out[((b * O_ + lane) * H_ + h) * W_ + w] = ALPHA * acc;
    }
}

extern "C" void kernel_launch(void* const* d_in, const int* in_sizes, int n_in,
                              void* d_out, int out_size) {
    const float* x     = (const float*)d_in[0];
    const float* theta = (const float*)d_in[1];
    float* out         = (float*)d_out;
    dim3 grid(W_ / WSEG, H_, B_);   // (2, 64, 4) = 512 CTAs
    ekv_kernel<<<grid, NT>>>(x, theta, out);
}